// round 4
// baseline (speedup 1.0000x reference)
#include <cuda_runtime.h>
#include <math_constants.h>
#include <cstddef>

// Problem constants
#define Bb 2
#define Qq 2048
#define Kk 2048
#define DMm 512
#define Hh 8
#define Ff 5
#define DHh 64
#define TK 64

// Scratch (alloc-free rule: __device__ globals)
__device__ float g_q[Bb * Qq * DMm];
__device__ float g_k[Bb * Kk * DMm];
__device__ float g_v[Bb * Kk * DMm];
__device__ float g_ctx[Bb * Qq * DMm];

// ---------------------------------------------------------------------------
// GEMM: C[M,512] = (A[M,512] @ W[512,512] + bias[512]) * scale
// 64x64 C-tile, 256 threads, 4x4 micro-tile, k-step 32, float4 global loads.
// (unchanged from round 2 — known good, 175us for merged QKV)
// ---------------------------------------------------------------------------
__device__ __forceinline__ void gemm512_body(
    const float* __restrict__ A, const float* __restrict__ W,
    const float* __restrict__ bias, float* __restrict__ C, float scale,
    int rowBase, int colBase)
{
    __shared__ __align__(16) float As[64][32];
    __shared__ __align__(16) float Ws[32][64];

    const int tid = threadIdx.x;
    const int tx = tid & 15;
    const int ty = tid >> 4;

    float acc[4][4];
#pragma unroll
    for (int i = 0; i < 4; ++i)
#pragma unroll
        for (int j = 0; j < 4; ++j) acc[i][j] = 0.f;

    const int ar = tid >> 3;            // 0..31 (two passes: +32)
    const int ac = (tid & 7) << 2;      // 0,4,..28
    const int wr = tid >> 4;            // 0..15 (two passes: +16)
    const int wc = (tid & 15) << 2;

    for (int k0 = 0; k0 < 512; k0 += 32) {
        __syncthreads();
#pragma unroll
        for (int p = 0; p < 2; ++p) {
            *reinterpret_cast<float4*>(&As[ar + p * 32][ac]) =
                *reinterpret_cast<const float4*>(
                    A + (size_t)(rowBase + ar + p * 32) * 512 + k0 + ac);
            *reinterpret_cast<float4*>(&Ws[wr + p * 16][wc]) =
                *reinterpret_cast<const float4*>(
                    W + (size_t)(k0 + wr + p * 16) * 512 + colBase + wc);
        }
        __syncthreads();
#pragma unroll
        for (int kk = 0; kk < 32; ++kk) {
            float a4[4];
#pragma unroll
            for (int i = 0; i < 4; ++i) a4[i] = As[ty * 4 + i][kk];
            float4 w4 = *reinterpret_cast<const float4*>(&Ws[kk][tx * 4]);
            float wv[4] = {w4.x, w4.y, w4.z, w4.w};
#pragma unroll
            for (int i = 0; i < 4; ++i)
#pragma unroll
                for (int j = 0; j < 4; ++j)
                    acc[i][j] = fmaf(a4[i], wv[j], acc[i][j]);
        }
    }

#pragma unroll
    for (int i = 0; i < 4; ++i) {
#pragma unroll
        for (int j = 0; j < 4; ++j) {
            int rr = rowBase + ty * 4 + i;
            int cc = colBase + tx * 4 + j;
            C[(size_t)rr * 512 + cc] = (acc[i][j] + bias[cc]) * scale;
        }
    }
}

__global__ __launch_bounds__(256) void qkv_gemm_kernel(
    const float* __restrict__ qs, const float* __restrict__ ks,
    const float* __restrict__ vs,
    const float* __restrict__ Wq, const float* __restrict__ bq,
    const float* __restrict__ Wk, const float* __restrict__ bk,
    const float* __restrict__ Wv, const float* __restrict__ bv,
    float* __restrict__ oq, float* __restrict__ ok, float* __restrict__ ov)
{
    const int rowBase = blockIdx.y * 64;
    const int colBase = blockIdx.x * 64;
    const int z = blockIdx.z;
    const float* A = (z == 0) ? qs : (z == 1) ? ks : vs;
    const float* W = (z == 0) ? Wq : (z == 1) ? Wk : Wv;
    const float* bias = (z == 0) ? bq : (z == 1) ? bk : bv;
    float* C = (z == 0) ? oq : (z == 1) ? ok : ov;
    const float scale = (z == 0) ? 0.125f : 1.0f;   // 1/sqrt(64)
    gemm512_body(A, W, bias, C, scale, rowBase, colBase);
}

__global__ __launch_bounds__(256) void out_gemm_kernel(
    const float* __restrict__ A, const float* __restrict__ W,
    const float* __restrict__ bias, float* __restrict__ C)
{
    gemm512_body(A, W, bias, C, 1.0f, blockIdx.y * 64, blockIdx.x * 64);
}

// ---------------------------------------------------------------------------
// Fused attention, 2 threads per query row (halved register state).
// Block: 256 threads -> 128 query rows. Grid: (Q/128, H, B).
// Each thread owns 32 of the 64 head dims; score via one shfl_xor.
// RBF basis functions split across the thread pair (f 0-2 / f 3-4) and
// folded into the partial sum BEFORE the shuffle.
// ---------------------------------------------------------------------------
__global__ __launch_bounds__(256) void attn_kernel(
    const float* __restrict__ qlocs, const float* __restrict__ klocs,
    const float* __restrict__ apar, const float* __restrict__ bpar,
    const float* __restrict__ cpar, const int* __restrict__ valid_lens)
{
    __shared__ __align__(16) float Ks[TK][DHh];
    __shared__ __align__(16) float Vs[TK][DHh];
    __shared__ float Ls[TK][2];
    __shared__ float sa[Ff], sb[Ff], sc[Ff];

    const int tid = threadIdx.x;
    const int row = tid >> 1;
    const int half = tid & 1;
    const int h = blockIdx.y;
    const int b = blockIdx.z;
    const int qrow = blockIdx.x * 128 + row;

    if (tid < Ff) {
        sa[tid] = apar[h * Ff + tid];
        sb[tid] = fabsf(bpar[h * Ff + tid]);
        sc[tid] = cpar[h * Ff + tid];
    }

    const float qx = qlocs[(size_t)(b * Qq + qrow) * 2 + 0];
    const float qy = qlocs[(size_t)(b * Qq + qrow) * 2 + 1];

    // This thread's 32-dim half of the (pre-scaled) query vector
    float qv[32];
    const float* qptr = g_q + (size_t)(b * Qq + qrow) * DMm + h * DHh + half * 32;
#pragma unroll
    for (int d = 0; d < 32; d += 4) {
        float4 t = *reinterpret_cast<const float4*>(qptr + d);
        qv[d] = t.x; qv[d + 1] = t.y; qv[d + 2] = t.z; qv[d + 3] = t.w;
    }

    float acc[32];
#pragma unroll
    for (int d = 0; d < 32; ++d) acc[d] = 0.f;
    float m = -CUDART_INF_F;
    float l = 0.f;

    const int kend = valid_lens[b];
    const int fstart = half * 3;             // 0 or 3
    const int fend = fstart + 3 - half;      // 3 or 5

    for (int kt0 = 0; kt0 < kend; kt0 += TK) {
        __syncthreads();
        // Cooperative tile load: 1024 float4 per array, 256 threads -> 4 each
#pragma unroll
        for (int i = 0; i < 4; ++i) {
            int v = tid + i * 256;           // 0..1023
            int r = v >> 4;
            int c = (v & 15) << 2;
            size_t base = (size_t)(b * Kk + kt0 + r) * DMm + h * DHh + c;
            *reinterpret_cast<float4*>(&Ks[r][c]) =
                *reinterpret_cast<const float4*>(g_k + base);
            *reinterpret_cast<float4*>(&Vs[r][c]) =
                *reinterpret_cast<const float4*>(g_v + base);
        }
        if (tid < TK * 2) {
            Ls[tid >> 1][tid & 1] = klocs[(size_t)(b * Kk + kt0) * 2 + tid];
        }
        __syncthreads();

        const int jmax = min(TK, kend - kt0);
#pragma unroll 1
        for (int j = 0; j < jmax; ++j) {
            // Partial dot over this thread's 32 dims (4 independent chains)
            const float4* kr = reinterpret_cast<const float4*>(&Ks[j][half * 32]);
            float s0 = 0.f, s1 = 0.f, s2 = 0.f, s3 = 0.f;
#pragma unroll
            for (int d4 = 0; d4 < 8; ++d4) {
                float4 k4 = kr[d4];
                s0 = fmaf(qv[4 * d4 + 0], k4.x, s0);
                s1 = fmaf(qv[4 * d4 + 1], k4.y, s1);
                s2 = fmaf(qv[4 * d4 + 2], k4.z, s2);
                s3 = fmaf(qv[4 * d4 + 3], k4.w, s3);
            }
            float sp = (s0 + s1) + (s2 + s3);

            // Partial TISA bias (this thread's basis subset)
            float dx = qx - Ls[j][0];
            float dy = qy - Ls[j][1];
            float dist = sqrtf(fmaf(dx, dx, dy * dy));
            for (int f = fstart; f < fend; ++f) {
                float t = dist - sc[f];
                sp = fmaf(sa[f], __expf(-sb[f] * t * t), sp);
            }

            // Combine the two halves
            float s = sp + __shfl_xor_sync(0xffffffffu, sp, 1);

            // Online softmax (rescale only when max moves)
            if (s > m) {
                float corr = __expf(m - s);   // exp(-inf)=0 handles first key
                l *= corr;
#pragma unroll
                for (int d = 0; d < 32; ++d) acc[d] *= corr;
                m = s;
            }
            float p = __expf(s - m);
            l += p;

            const float4* vr = reinterpret_cast<const float4*>(&Vs[j][half * 32]);
#pragma unroll
            for (int d4 = 0; d4 < 8; ++d4) {
                float4 v4 = vr[d4];
                acc[4 * d4 + 0] = fmaf(p, v4.x, acc[4 * d4 + 0]);
                acc[4 * d4 + 1] = fmaf(p, v4.y, acc[4 * d4 + 1]);
                acc[4 * d4 + 2] = fmaf(p, v4.z, acc[4 * d4 + 2]);
                acc[4 * d4 + 3] = fmaf(p, v4.w, acc[4 * d4 + 3]);
            }
        }
    }

    const float invl = 1.f / l;
    float* optr = g_ctx + (size_t)(b * Qq + qrow) * DMm + h * DHh + half * 32;
#pragma unroll
    for (int d = 0; d < 32; d += 4) {
        float4 t;
        t.x = acc[d] * invl;
        t.y = acc[d + 1] * invl;
        t.z = acc[d + 2] * invl;
        t.w = acc[d + 3] * invl;
        *reinterpret_cast<float4*>(optr + d) = t;
    }
}

// ---------------------------------------------------------------------------
// Launch
// ---------------------------------------------------------------------------
extern "C" void kernel_launch(void* const* d_in, const int* in_sizes, int n_in,
                              void* d_out, int out_size)
{
    const float* qs      = (const float*)d_in[0];
    const float* ks      = (const float*)d_in[1];
    const float* vs      = (const float*)d_in[2];
    const float* qs_locs = (const float*)d_in[3];
    const float* ks_locs = (const float*)d_in[4];
    const float* Wq      = (const float*)d_in[5];
    const float* bq      = (const float*)d_in[6];
    const float* Wk      = (const float*)d_in[7];
    const float* bk      = (const float*)d_in[8];
    const float* Wv      = (const float*)d_in[9];
    const float* bv      = (const float*)d_in[10];
    const float* Wo      = (const float*)d_in[11];
    const float* bo      = (const float*)d_in[12];
    const float* ap      = (const float*)d_in[13];
    const float* bp      = (const float*)d_in[14];
    const float* cp      = (const float*)d_in[15];
    const int*   vlen    = (const int*)d_in[16];
    float* out           = (float*)d_out;

    float *pq, *pk, *pv, *pctx;
    cudaGetSymbolAddress((void**)&pq,   g_q);
    cudaGetSymbolAddress((void**)&pk,   g_k);
    cudaGetSymbolAddress((void**)&pv,   g_v);
    cudaGetSymbolAddress((void**)&pctx, g_ctx);

    dim3 ggrid(512 / 64, (Bb * Qq) / 64, 3);  // (8, 64, 3)
    qkv_gemm_kernel<<<ggrid, 256>>>(qs, ks, vs, Wq, bq, Wk, bk, Wv, bv,
                                    pq, pk, pv);

    dim3 agrid(Qq / 128, Hh, Bb);  // (16, 8, 2)
    attn_kernel<<<agrid, 256>>>(qs_locs, ks_locs, ap, bp, cp, vlen);

    dim3 ogrid(512 / 64, (Bb * Qq) / 64);
    out_gemm_kernel<<<ogrid, 256>>>(pctx, Wo, bo, out);
}

// round 5
// speedup vs baseline: 1.5650x; 1.5650x over previous
#include <cuda_runtime.h>
#include <math_constants.h>
#include <cstddef>

// Problem constants
#define Bb 2
#define Qq 2048
#define Kk 2048
#define DMm 512
#define Hh 8
#define Ff 5
#define DHh 64
#define TK 64

// Bias lookup table
#define NT 2048
#define DMAXV 14.15f   // > sqrt(200) = max possible distance for locs in [0,10]^2

// Scratch (alloc-free rule: __device__ globals)
__device__ float g_q[Bb * Qq * DMm];
__device__ float g_k[Bb * Kk * DMm];
__device__ float g_v[Bb * Kk * DMm];
__device__ float g_ctx[Bb * Qq * DMm];
__device__ float g_btab[Hh * NT];

// ---------------------------------------------------------------------------
// Build per-head bias table: g_btab[h][i] = sum_f a*exp(-|b|*(d_i - c)^2),
// d_i = i * DMAX/(NT-1).  Grid: (Hh), 256 threads.
// ---------------------------------------------------------------------------
__global__ void build_bias_table(const float* __restrict__ apar,
                                 const float* __restrict__ bpar,
                                 const float* __restrict__ cpar)
{
    const int h = blockIdx.x;
    float af[Ff], bf[Ff], cf[Ff];
#pragma unroll
    for (int f = 0; f < Ff; ++f) {
        af[f] = apar[h * Ff + f];
        bf[f] = fabsf(bpar[h * Ff + f]);
        cf[f] = cpar[h * Ff + f];
    }
    const float step = DMAXV / (float)(NT - 1);
    for (int i = threadIdx.x; i < NT; i += blockDim.x) {
        float d = i * step;
        float s = 0.f;
#pragma unroll
        for (int f = 0; f < Ff; ++f) {
            float t = d - cf[f];
            s = fmaf(af[f], __expf(-bf[f] * t * t), s);
        }
        g_btab[h * NT + i] = s;
    }
}

// ---------------------------------------------------------------------------
// GEMM: C[M,512] = (A[M,512] @ W[512,512] + bias[512]) * scale
// 64x64 C-tile, 256 threads, 4x4 micro-tile, k-step 32, float4 global loads.
// ---------------------------------------------------------------------------
__device__ __forceinline__ void gemm512_body(
    const float* __restrict__ A, const float* __restrict__ W,
    const float* __restrict__ bias, float* __restrict__ C, float scale,
    int rowBase, int colBase)
{
    __shared__ __align__(16) float As[64][32];
    __shared__ __align__(16) float Ws[32][64];

    const int tid = threadIdx.x;
    const int tx = tid & 15;
    const int ty = tid >> 4;

    float acc[4][4];
#pragma unroll
    for (int i = 0; i < 4; ++i)
#pragma unroll
        for (int j = 0; j < 4; ++j) acc[i][j] = 0.f;

    const int ar = tid >> 3;            // 0..31 (two passes: +32)
    const int ac = (tid & 7) << 2;      // 0,4,..28
    const int wr = tid >> 4;            // 0..15 (two passes: +16)
    const int wc = (tid & 15) << 2;

    for (int k0 = 0; k0 < 512; k0 += 32) {
        __syncthreads();
#pragma unroll
        for (int p = 0; p < 2; ++p) {
            *reinterpret_cast<float4*>(&As[ar + p * 32][ac]) =
                *reinterpret_cast<const float4*>(
                    A + (size_t)(rowBase + ar + p * 32) * 512 + k0 + ac);
            *reinterpret_cast<float4*>(&Ws[wr + p * 16][wc]) =
                *reinterpret_cast<const float4*>(
                    W + (size_t)(k0 + wr + p * 16) * 512 + colBase + wc);
        }
        __syncthreads();
#pragma unroll
        for (int kk = 0; kk < 32; ++kk) {
            float a4[4];
#pragma unroll
            for (int i = 0; i < 4; ++i) a4[i] = As[ty * 4 + i][kk];
            float4 w4 = *reinterpret_cast<const float4*>(&Ws[kk][tx * 4]);
            float wv[4] = {w4.x, w4.y, w4.z, w4.w};
#pragma unroll
            for (int i = 0; i < 4; ++i)
#pragma unroll
                for (int j = 0; j < 4; ++j)
                    acc[i][j] = fmaf(a4[i], wv[j], acc[i][j]);
        }
    }

#pragma unroll
    for (int i = 0; i < 4; ++i) {
#pragma unroll
        for (int j = 0; j < 4; ++j) {
            int rr = rowBase + ty * 4 + i;
            int cc = colBase + tx * 4 + j;
            C[(size_t)rr * 512 + cc] = (acc[i][j] + bias[cc]) * scale;
        }
    }
}

__global__ __launch_bounds__(256) void qkv_gemm_kernel(
    const float* __restrict__ qs, const float* __restrict__ ks,
    const float* __restrict__ vs,
    const float* __restrict__ Wq, const float* __restrict__ bq,
    const float* __restrict__ Wk, const float* __restrict__ bk,
    const float* __restrict__ Wv, const float* __restrict__ bv,
    float* __restrict__ oq, float* __restrict__ ok, float* __restrict__ ov)
{
    const int rowBase = blockIdx.y * 64;
    const int colBase = blockIdx.x * 64;
    const int z = blockIdx.z;
    const float* A = (z == 0) ? qs : (z == 1) ? ks : vs;
    const float* W = (z == 0) ? Wq : (z == 1) ? Wk : Wv;
    const float* bias = (z == 0) ? bq : (z == 1) ? bk : bv;
    float* C = (z == 0) ? oq : (z == 1) ? ok : ov;
    const float scale = (z == 0) ? 0.125f : 1.0f;   // 1/sqrt(64)
    gemm512_body(A, W, bias, C, scale, rowBase, colBase);
}

__global__ __launch_bounds__(256) void out_gemm_kernel(
    const float* __restrict__ A, const float* __restrict__ W,
    const float* __restrict__ bias, float* __restrict__ C)
{
    gemm512_body(A, W, bias, C, 1.0f, blockIdx.y * 64, blockIdx.x * 64);
}

// ---------------------------------------------------------------------------
// Fused attention — EXACT round-1 structure (best measured: 556us), with the
// 5-exp TISA bias replaced by a shared-memory LUT + linear interpolation.
// One thread per query row, 128 threads/block. Grid: (Q/128, H, B).
// ---------------------------------------------------------------------------
__global__ __launch_bounds__(128) void attn_kernel(
    const float* __restrict__ qlocs, const float* __restrict__ klocs,
    const int* __restrict__ valid_lens)
{
    __shared__ __align__(16) float Ks[TK][DHh];
    __shared__ __align__(16) float Vs[TK][DHh];
    __shared__ float Ls[TK][2];
    __shared__ float Tb[NT];

    const int tid = threadIdx.x;
    const int h = blockIdx.y;
    const int b = blockIdx.z;
    const int qrow = blockIdx.x * 128 + tid;

    // Load this head's bias table: 2048 floats, 128 threads -> float4 x4 each
#pragma unroll
    for (int i = 0; i < 4; ++i) {
        int v = (tid + i * 128) << 2;
        *reinterpret_cast<float4*>(&Tb[v]) =
            *reinterpret_cast<const float4*>(g_btab + h * NT + v);
    }

    const float qx = qlocs[(size_t)(b * Qq + qrow) * 2 + 0];
    const float qy = qlocs[(size_t)(b * Qq + qrow) * 2 + 1];
    const float inv_step = (float)(NT - 1) / DMAXV;

    // Query vector (already scaled by 1/sqrt(DH) in the projection GEMM)
    float qv[DHh];
    const float* qptr = g_q + (size_t)(b * Qq + qrow) * DMm + h * DHh;
#pragma unroll
    for (int d = 0; d < DHh; d += 4) {
        float4 t = *reinterpret_cast<const float4*>(qptr + d);
        qv[d] = t.x; qv[d + 1] = t.y; qv[d + 2] = t.z; qv[d + 3] = t.w;
    }

    float acc[DHh];
#pragma unroll
    for (int d = 0; d < DHh; ++d) acc[d] = 0.f;
    float m = -CUDART_INF_F;
    float l = 0.f;

    const int kend = valid_lens[b];

    for (int kt0 = 0; kt0 < kend; kt0 += TK) {
        __syncthreads();
        // Cooperative load: 1024 float4 per array; 128 threads -> 8 each.
#pragma unroll
        for (int i = 0; i < 8; ++i) {
            int v = tid + i * 128;           // 0..1023
            int r = v >> 4;
            int c = (v & 15) << 2;
            size_t base = (size_t)(b * Kk + kt0 + r) * DMm + h * DHh + c;
            *reinterpret_cast<float4*>(&Ks[r][c]) =
                *reinterpret_cast<const float4*>(g_k + base);
            *reinterpret_cast<float4*>(&Vs[r][c]) =
                *reinterpret_cast<const float4*>(g_v + base);
        }
        if (tid < TK * 2) {
            Ls[tid >> 1][tid & 1] = klocs[(size_t)(b * Kk + kt0) * 2 + tid];
        }
        __syncthreads();

        const int jmax = min(TK, kend - kt0);
        for (int j = 0; j < jmax; ++j) {
            // q . k  (shared broadcast: all threads read the same address)
            float s = 0.f;
#pragma unroll
            for (int d = 0; d < DHh; ++d) s = fmaf(qv[d], Ks[j][d], s);

            // TISA RBF bias via LUT + linear interpolation
            float dx = qx - Ls[j][0];
            float dy = qy - Ls[j][1];
            float dist = sqrtf(fmaf(dx, dx, dy * dy));
            float t = dist * inv_step;
            int i0 = (int)t;
            i0 = min(i0, NT - 2);
            float frac = t - (float)i0;
            float b0 = Tb[i0];
            float b1 = Tb[i0 + 1];
            s += fmaf(frac, b1 - b0, b0);

            // Online softmax: rescale only when max changes (rare)
            if (s > m) {
                float corr = __expf(m - s);   // __expf(-inf)=0 handles first key
                l *= corr;
#pragma unroll
                for (int d = 0; d < DHh; ++d) acc[d] *= corr;
                m = s;
            }
            float p = __expf(s - m);
            l += p;
#pragma unroll
            for (int d = 0; d < DHh; ++d) acc[d] = fmaf(p, Vs[j][d], acc[d]);
        }
    }

    const float invl = 1.f / l;
    float* optr = g_ctx + (size_t)(b * Qq + qrow) * DMm + h * DHh;
#pragma unroll
    for (int d = 0; d < DHh; d += 4) {
        float4 t;
        t.x = acc[d] * invl;
        t.y = acc[d + 1] * invl;
        t.z = acc[d + 2] * invl;
        t.w = acc[d + 3] * invl;
        *reinterpret_cast<float4*>(optr + d) = t;
    }
}

// ---------------------------------------------------------------------------
// Launch
// ---------------------------------------------------------------------------
extern "C" void kernel_launch(void* const* d_in, const int* in_sizes, int n_in,
                              void* d_out, int out_size)
{
    const float* qs      = (const float*)d_in[0];
    const float* ks      = (const float*)d_in[1];
    const float* vs      = (const float*)d_in[2];
    const float* qs_locs = (const float*)d_in[3];
    const float* ks_locs = (const float*)d_in[4];
    const float* Wq      = (const float*)d_in[5];
    const float* bq      = (const float*)d_in[6];
    const float* Wk      = (const float*)d_in[7];
    const float* bk      = (const float*)d_in[8];
    const float* Wv      = (const float*)d_in[9];
    const float* bv      = (const float*)d_in[10];
    const float* Wo      = (const float*)d_in[11];
    const float* bo      = (const float*)d_in[12];
    const float* ap      = (const float*)d_in[13];
    const float* bp      = (const float*)d_in[14];
    const float* cp      = (const float*)d_in[15];
    const int*   vlen    = (const int*)d_in[16];
    float* out           = (float*)d_out;

    float *pq, *pk, *pv, *pctx;
    cudaGetSymbolAddress((void**)&pq,   g_q);
    cudaGetSymbolAddress((void**)&pk,   g_k);
    cudaGetSymbolAddress((void**)&pv,   g_v);
    cudaGetSymbolAddress((void**)&pctx, g_ctx);

    build_bias_table<<<Hh, 256>>>(ap, bp, cp);

    dim3 ggrid(512 / 64, (Bb * Qq) / 64, 3);  // (8, 64, 3)
    qkv_gemm_kernel<<<ggrid, 256>>>(qs, ks, vs, Wq, bq, Wk, bk, Wv, bv,
                                    pq, pk, pv);

    dim3 agrid(Qq / 128, Hh, Bb);  // (16, 8, 2)
    attn_kernel<<<agrid, 128>>>(qs_locs, ks_locs, vlen);

    dim3 ogrid(512 / 64, (Bb * Qq) / 64);
    out_gemm_kernel<<<ogrid, 256>>>(pctx, Wo, bo, out);
}